// round 1
// baseline (speedup 1.0000x reference)
#include <cuda_runtime.h>

// Problem constants
#define Bb   128
#define Fdim 1536
#define Ed   512
#define Hd   512
#define H4   2048
#define Vd   10000
#define Tl   40
#define BT   (Bb*Tl)   // 5120

// ---------------- scratch (static device memory; no allocations) -------------
__device__ float g_seq[(size_t)BT * Ed];        // [T*B, E]  row r = t*B + b
__device__ float g_xg[(size_t)BT * H4];         // [T*B, 4H] row r = t*B + b
__device__ float g_hidden[(size_t)BT * Hd];     // [B*T, H]  row r = b*T + t
__device__ float g_h[Bb * Hd];
__device__ float g_c[Bb * Hd];
__device__ float g_gates[Bb * H4];

__device__ __forceinline__ float sigmoidf_(float x) { return 1.0f / (1.0f + expf(-x)); }

// ---------------- generic tiled fp32 GEMM:  C = A @ B^T (+bias[n]) (+add[m,n])
// A: [M,K] row-major, B: [N,K] row-major. M % BM == 0, K % BK == 0 assumed.
// N may be ragged (guarded). 256 threads per block.
template<int BM, int BN, int BK, int TM, int TN>
__global__ void gemm_tn(const float* __restrict__ A,
                        const float* __restrict__ Bw,
                        const float* __restrict__ bias,   // [N] or nullptr
                        const float* __restrict__ add,    // [M,N] or nullptr
                        float* __restrict__ C,
                        int M, int N, int K)
{
    constexpr int NT = (BM / TM) * (BN / TN);
    static_assert(NT == 256, "need 256 threads");
    __shared__ float As[BK][BM];
    __shared__ float Bs[BK][BN];

    const int m0 = blockIdx.y * BM;
    const int n0 = blockIdx.x * BN;
    const int tid = threadIdx.x;
    constexpr int NTX = BN / TN;
    const int tc = tid % NTX;           // n direction
    const int tr = tid / NTX;           // m direction

    float acc[TM][TN];
    #pragma unroll
    for (int i = 0; i < TM; i++)
        #pragma unroll
        for (int j = 0; j < TN; j++) acc[i][j] = 0.0f;

    constexpr int A_LD4 = BM * BK / 4;  // float4 loads for A tile
    constexpr int B_LD4 = BN * BK / 4;
    constexpr int K4 = BK / 4;

    for (int k0 = 0; k0 < K; k0 += BK) {
        // load A tile (transpose into As[k][m])
        #pragma unroll
        for (int i = tid; i < A_LD4; i += NT) {
            int row = i / K4;
            int kc  = (i % K4) * 4;
            float4 v = *reinterpret_cast<const float4*>(
                A + (size_t)(m0 + row) * K + k0 + kc);
            As[kc + 0][row] = v.x; As[kc + 1][row] = v.y;
            As[kc + 2][row] = v.z; As[kc + 3][row] = v.w;
        }
        // load B tile (transpose into Bs[k][n]); guard ragged N
        #pragma unroll
        for (int i = tid; i < B_LD4; i += NT) {
            int row = i / K4;
            int kc  = (i % K4) * 4;
            float4 v = make_float4(0.f, 0.f, 0.f, 0.f);
            if (n0 + row < N)
                v = *reinterpret_cast<const float4*>(
                    Bw + (size_t)(n0 + row) * K + k0 + kc);
            Bs[kc + 0][row] = v.x; Bs[kc + 1][row] = v.y;
            Bs[kc + 2][row] = v.z; Bs[kc + 3][row] = v.w;
        }
        __syncthreads();

        #pragma unroll
        for (int k = 0; k < BK; k++) {
            float ra[TM], rb[TN];
            #pragma unroll
            for (int i = 0; i < TM; i++) ra[i] = As[k][tr * TM + i];
            #pragma unroll
            for (int j = 0; j < TN; j++) rb[j] = Bs[k][tc * TN + j];
            #pragma unroll
            for (int i = 0; i < TM; i++)
                #pragma unroll
                for (int j = 0; j < TN; j++)
                    acc[i][j] = fmaf(ra[i], rb[j], acc[i][j]);
        }
        __syncthreads();
    }

    // epilogue
    #pragma unroll
    for (int i = 0; i < TM; i++) {
        int m = m0 + tr * TM + i;
        #pragma unroll
        for (int j = 0; j < TN; j++) {
            int n = n0 + tc * TN + j;
            if (n < N) {
                float v = acc[i][j];
                if (bias) v += bias[n];
                if (add)  v += add[(size_t)m * N + n];
                C[(size_t)m * N + n] = v;
            }
        }
    }
}

// ---------------- gather word embeddings into g_seq rows t>=1 ---------------
__global__ void gather_emb(const int* __restrict__ seqs,
                           const float* __restrict__ emb)
{
    int bid = blockIdx.x;              // 0 .. (T-1)*B - 1
    int t1  = bid / Bb;                // 0..38  (=> t = t1+1)
    int b   = bid % Bb;
    int word = seqs[b * (Tl - 1) + t1];
    const float4* src = reinterpret_cast<const float4*>(emb + (size_t)word * Ed);
    float4* dst = reinterpret_cast<float4*>(
        g_seq + (size_t)((t1 + 1) * Bb + b) * Ed);
    for (int i = threadIdx.x; i < Ed / 4; i += blockDim.x) dst[i] = src[i];
}

// ---------------- zero h, c ---------------------------------------------------
__global__ void init_state()
{
    int i = blockIdx.x * blockDim.x + threadIdx.x;
    if (i < Bb * Hd) { g_h[i] = 0.0f; g_c[i] = 0.0f; }
}

// ---------------- fused LSTM cell update -------------------------------------
__global__ void lstm_cell(int t)
{
    int idx = blockIdx.x * blockDim.x + threadIdx.x;   // 0 .. B*H-1
    if (idx >= Bb * Hd) return;
    int b = idx >> 9;          // /512
    int j = idx & 511;
    const float* gb = g_gates + (size_t)b * H4;
    float ig = sigmoidf_(gb[j]);
    float fg = sigmoidf_(gb[Hd + j]);
    float gg = tanhf(gb[2 * Hd + j]);
    float og = sigmoidf_(gb[3 * Hd + j]);
    float c = fmaf(fg, g_c[idx], ig * gg);
    g_c[idx] = c;
    float h = og * tanhf(c);
    g_h[idx] = h;
    g_hidden[((size_t)b * Tl + t) * Hd + j] = h;
}

// ---------------- launch ------------------------------------------------------
extern "C" void kernel_launch(void* const* d_in, const int* in_sizes, int n_in,
                              void* d_out, int out_size)
{
    const float* features = (const float*)d_in[0];   // [B,F]
    const int*   seqs     = (const int*)  d_in[1];   // [B,T-1]
    // d_in[2] = lengths (unused)
    const float* W_in  = (const float*)d_in[3];      // [E,F]
    const float* b_in  = (const float*)d_in[4];      // [E]
    const float* emb   = (const float*)d_in[5];      // [V,E]
    const float* W_ih  = (const float*)d_in[6];      // [4H,E]
    const float* W_hh  = (const float*)d_in[7];      // [4H,H]
    const float* b_ih  = (const float*)d_in[8];      // [4H]
    const float* b_hh  = (const float*)d_in[9];      // [4H]
    const float* W_out = (const float*)d_in[10];     // [V,H]
    const float* b_out = (const float*)d_in[11];     // [V]
    float* out = (float*)d_out;                      // [B,T,V]

    float *p_seq, *p_xg, *p_hidden, *p_h, *p_gates;
    cudaGetSymbolAddress((void**)&p_seq,    g_seq);
    cudaGetSymbolAddress((void**)&p_xg,     g_xg);
    cudaGetSymbolAddress((void**)&p_hidden, g_hidden);
    cudaGetSymbolAddress((void**)&p_h,      g_h);
    cudaGetSymbolAddress((void**)&p_gates,  g_gates);

    // 1) x0 = features @ W_in^T + b_in  -> rows [0,128) of g_seq (t=0 slice)
    //    M=128, N=512, K=1536 ; small-tile config for parallelism
    {
        dim3 grid(Ed / 64, Bb / 32);
        gemm_tn<32, 64, 8, 2, 4><<<grid, 256>>>(
            features, W_in, b_in, nullptr, p_seq, Bb, Ed, Fdim);
    }

    // 2) gather embeddings for t = 1..T-1
    gather_emb<<<(Tl - 1) * Bb, 128>>>(seqs, emb);

    // 3) xg = g_seq @ W_ih^T + b_ih   [5120, 2048], K=512
    {
        dim3 grid(H4 / 128, BT / 128);
        gemm_tn<128, 128, 8, 8, 8><<<grid, 256>>>(
            p_seq, W_ih, b_ih, nullptr, p_xg, BT, H4, Ed);
    }

    // 4) init h, c = 0
    init_state<<<(Bb * Hd + 255) / 256, 256>>>();

    // 5) recurrence: 40 steps of (gates GEMM + fused addend) -> cell update
    for (int t = 0; t < Tl; t++) {
        dim3 grid(H4 / 64, Bb / 32);
        const float* xg_t = p_xg + (size_t)t * Bb * H4;
        gemm_tn<32, 64, 8, 2, 4><<<grid, 256>>>(
            p_h, W_hh, b_hh, xg_t, p_gates, Bb, H4, Hd);
        lstm_cell<<<(Bb * Hd + 255) / 256, 256>>>(t);
    }

    // 6) out = hiddens @ W_out^T + b_out   [5120, 10000], K=512
    {
        dim3 grid((Vd + 127) / 128, BT / 128);
        gemm_tn<128, 128, 8, 8, 8><<<grid, 256>>>(
            p_hidden, W_out, b_out, nullptr, out, BT, Vd, Hd);
    }
}

// round 2
// speedup vs baseline: 2.1309x; 2.1309x over previous
#include <cuda_runtime.h>
#include <cuda_bf16.h>
#include <cstdint>

// Problem constants
#define Bb   128
#define Fdim 1536
#define Ed   512
#define Hd   512
#define H4   2048
#define Vd   10000
#define Tl   40
#define BT   (Bb*Tl)     // 5120
#define K3E  (3*Ed)      // 1536
#define K3F  (3*Fdim)    // 4608

// ---------------- scratch (static device memory) -----------------------------
__device__ float g_seq[(size_t)BT * Ed];        // [T*B, E]  row r = t*B + b
__device__ float g_xg[(size_t)BT * H4];         // [T*B, 4H]
__device__ float g_hidden[(size_t)BT * Hd];     // [B*T, H]  row r = b*T + t
__device__ float g_h[Bb * Hd];
__device__ float g_c[Bb * Hd];

// split-bf16 operand buffers (K-concatenated 3-way split)
__device__ __align__(16) __nv_bfloat16 s_feat[(size_t)Bb * K3F];
__device__ __align__(16) __nv_bfloat16 s_Win [(size_t)Ed * K3F];
__device__ __align__(16) __nv_bfloat16 s_seq [(size_t)BT * K3E];
__device__ __align__(16) __nv_bfloat16 s_Wih [(size_t)H4 * K3E];
__device__ __align__(16) __nv_bfloat16 s_hid [(size_t)BT * K3E];
__device__ __align__(16) __nv_bfloat16 s_Wout[(size_t)Vd * K3E];

__device__ __forceinline__ float sigmoidf_(float x) { return 1.0f / (1.0f + __expf(-x)); }

__device__ __forceinline__ uint32_t smem_u32(const void* p) {
    return (uint32_t)__cvta_generic_to_shared(p);
}

// ---------------- split fp32 -> 3-segment bf16 --------------------------------
// MODE_B==0 (A-side): [hi | hi | lo]      MODE_B==1 (B-side): [hi | lo | hi]
template<int MODE_B>
__global__ void split3(const float* __restrict__ X, __nv_bfloat16* __restrict__ Y,
                       int M, int K)
{
    size_t i = (size_t)blockIdx.x * blockDim.x + threadIdx.x;
    size_t total = (size_t)M * K;
    if (i >= total) return;
    int m = (int)(i / K), k = (int)(i % K);
    float x = X[i];
    __nv_bfloat16 hi = __float2bfloat16_rn(x);
    __nv_bfloat16 lo = __float2bfloat16_rn(x - __bfloat162float(hi));
    __nv_bfloat16* row = Y + (size_t)m * (3 * K);
    if (MODE_B) { row[k] = hi; row[K + k] = lo; row[2 * K + k] = hi; }
    else        { row[k] = hi; row[K + k] = hi; row[2 * K + k] = lo; }
}

// ---------------- bf16 tensor-core GEMM:  C = A @ B^T + bias ------------------
// A: [M, K] bf16 row-major (M % 128 == 0), B: [N, K] bf16 row-major (N ragged OK),
// K % 32 == 0. Block tile 128x128x32, 8 warps, warp tile 64x32, mma m16n8k16.
#define STRIDEg 40   // smem row stride in bf16 elems (80B) -> conflict-free ldmatrix

__global__ void __launch_bounds__(256)
gemm_bf16(const __nv_bfloat16* __restrict__ A,
          const __nv_bfloat16* __restrict__ B,
          const float* __restrict__ bias,
          float* __restrict__ C,
          int M, int N, int K)
{
    __shared__ __align__(16) __nv_bfloat16 As[2][128 * STRIDEg];
    __shared__ __align__(16) __nv_bfloat16 Bs[2][128 * STRIDEg];

    const int tid  = threadIdx.x;
    const int warp = tid >> 5, lane = tid & 31;
    const int wm = (warp >> 2) * 64;   // warp M origin in tile
    const int wn = (warp & 3) * 32;    // warp N origin in tile
    const int m0 = blockIdx.y * 128, n0 = blockIdx.x * 128;

    float acc[4][4][4];
    #pragma unroll
    for (int i = 0; i < 4; i++)
        #pragma unroll
        for (int j = 0; j < 4; j++)
            #pragma unroll
            for (int r = 0; r < 4; r++) acc[i][j][r] = 0.0f;

    const int KT = K / 32;

    // stage loader: 128 rows x 32 cols bf16 per matrix = 512 x 16B chunks
    auto load_tile = [&](int buf, int kt) {
        const int k0 = kt * 32;
        #pragma unroll
        for (int it = 0; it < 2; it++) {
            int task = tid + it * 256;
            int r = task >> 2, c = task & 3;
            uint32_t dst = smem_u32(&As[buf][r * STRIDEg + c * 8]);
            const void* src = A + (size_t)(m0 + r) * K + k0 + c * 8;
            asm volatile("cp.async.cg.shared.global [%0],[%1],16;\n" :: "r"(dst), "l"(src));
        }
        #pragma unroll
        for (int it = 0; it < 2; it++) {
            int task = tid + it * 256;
            int r = task >> 2, c = task & 3;
            if (n0 + r < N) {
                uint32_t dst = smem_u32(&Bs[buf][r * STRIDEg + c * 8]);
                const void* src = B + (size_t)(n0 + r) * K + k0 + c * 8;
                asm volatile("cp.async.cg.shared.global [%0],[%1],16;\n" :: "r"(dst), "l"(src));
            }
        }
        asm volatile("cp.async.commit_group;\n");
    };

    load_tile(0, 0);
    int buf = 0;
    for (int kt = 0; kt < KT; kt++) {
        if (kt + 1 < KT) {
            load_tile(buf ^ 1, kt + 1);
            asm volatile("cp.async.wait_group 1;\n");
        } else {
            asm volatile("cp.async.wait_group 0;\n");
        }
        __syncthreads();

        #pragma unroll
        for (int kk = 0; kk < 32; kk += 16) {
            // A fragments: 4 m-tiles of 16x16
            uint32_t afr[4][4];
            #pragma unroll
            for (int i = 0; i < 4; i++) {
                int row = wm + i * 16 + (lane & 15);
                int col = kk + (lane >> 4) * 8;
                uint32_t addr = smem_u32(&As[buf][row * STRIDEg + col]);
                asm volatile("ldmatrix.sync.aligned.m8n8.x4.shared.b16 {%0,%1,%2,%3},[%4];"
                             : "=r"(afr[i][0]), "=r"(afr[i][1]), "=r"(afr[i][2]), "=r"(afr[i][3])
                             : "r"(addr));
            }
            // B fragments: 4 n-subtiles of 8, fetched as 2 x ldmatrix.x4 (16 rows each)
            uint32_t bfr[4][2];
            #pragma unroll
            for (int j = 0; j < 2; j++) {
                int grp = lane >> 3;
                int row = wn + j * 16 + (grp >> 1) * 8 + (lane & 7);
                int col = kk + (grp & 1) * 8;
                uint32_t addr = smem_u32(&Bs[buf][row * STRIDEg + col]);
                uint32_t r0, r1, r2, r3;
                asm volatile("ldmatrix.sync.aligned.m8n8.x4.shared.b16 {%0,%1,%2,%3},[%4];"
                             : "=r"(r0), "=r"(r1), "=r"(r2), "=r"(r3) : "r"(addr));
                bfr[j * 2][0] = r0; bfr[j * 2][1] = r1;
                bfr[j * 2 + 1][0] = r2; bfr[j * 2 + 1][1] = r3;
            }
            #pragma unroll
            for (int i = 0; i < 4; i++)
                #pragma unroll
                for (int j = 0; j < 4; j++) {
                    asm volatile(
                        "mma.sync.aligned.m16n8k16.row.col.f32.bf16.bf16.f32 "
                        "{%0,%1,%2,%3},{%4,%5,%6,%7},{%8,%9},{%0,%1,%2,%3};"
                        : "+f"(acc[i][j][0]), "+f"(acc[i][j][1]),
                          "+f"(acc[i][j][2]), "+f"(acc[i][j][3])
                        : "r"(afr[i][0]), "r"(afr[i][1]), "r"(afr[i][2]), "r"(afr[i][3]),
                          "r"(bfr[j][0]), "r"(bfr[j][1]));
                }
        }
        __syncthreads();
        buf ^= 1;
    }

    // epilogue
    const int mrow = lane >> 2, nc2 = (lane & 3) * 2;
    #pragma unroll
    for (int i = 0; i < 4; i++) {
        int gm = m0 + wm + i * 16 + mrow;
        float* Crow0 = C + (size_t)gm * N;
        float* Crow1 = C + (size_t)(gm + 8) * N;
        #pragma unroll
        for (int j = 0; j < 4; j++) {
            int gn = n0 + wn + j * 8 + nc2;
            if (gn < N) {
                float bv = bias[gn];
                Crow0[gn] = acc[i][j][0] + bv;
                Crow1[gn] = acc[i][j][2] + bv;
            }
            if (gn + 1 < N) {
                float bv = bias[gn + 1];
                Crow0[gn + 1] = acc[i][j][1] + bv;
                Crow1[gn + 1] = acc[i][j][3] + bv;
            }
        }
    }
}

// ---------------- gather word embeddings into g_seq rows t>=1 -----------------
__global__ void gather_emb(const int* __restrict__ seqs,
                           const float* __restrict__ emb)
{
    int bid = blockIdx.x;              // 0 .. (T-1)*B - 1
    int t1  = bid / Bb;                // 0..38  (=> t = t1+1)
    int b   = bid % Bb;
    int word = seqs[b * (Tl - 1) + t1];
    const float4* src = reinterpret_cast<const float4*>(emb + (size_t)word * Ed);
    float4* dst = reinterpret_cast<float4*>(g_seq + (size_t)((t1 + 1) * Bb + b) * Ed);
    for (int i = threadIdx.x; i < Ed / 4; i += blockDim.x) dst[i] = src[i];
}

// ---------------- zero h, c ----------------------------------------------------
__global__ void init_state()
{
    int i = blockIdx.x * blockDim.x + threadIdx.x;
    if (i < Bb * Hd) { g_h[i] = 0.0f; g_c[i] = 0.0f; }
}

// ---------------- fused LSTM step: gates GEMM + cell ---------------------------
// grid: (jt=0..31, bt=0..3). Block computes 32 b-rows x 16 j's x 4 gates.
// gates = h @ W_hh^T (K=512) + xg_t + b_hh, then cell update.
__global__ void __launch_bounds__(256)
lstm_step(const float* __restrict__ Whh,   // [4H, H]
          const float* __restrict__ bhh,   // [4H]
          const float* __restrict__ xg_t,  // [B, 4H]
          int t)
{
    __shared__ float As2[32][33];   // [k][m(b)]
    __shared__ float Bs2[32][65];   // [k][n]  n = gate*16 + jj (64)
    __shared__ float Gs [32][65];   // gates [b][n]

    const int tid = threadIdx.x;
    const int jt = blockIdx.x;           // 0..31, 16 j's each
    const int b0 = blockIdx.y * 32;      // batch origin
    const int tr = tid >> 4, tc = tid & 15;

    float acc[2][4];
    #pragma unroll
    for (int i = 0; i < 2; i++)
        #pragma unroll
        for (int j = 0; j < 4; j++) acc[i][j] = 0.0f;

    for (int kc = 0; kc < Hd; kc += 32) {
        // load h tile: 32 b x 32 k  (256 float4 tasks)
        {
            int r = tid >> 3, c = tid & 7;
            float4 v = *reinterpret_cast<const float4*>(
                g_h + (size_t)(b0 + r) * Hd + kc + c * 4);
            As2[c * 4 + 0][r] = v.x; As2[c * 4 + 1][r] = v.y;
            As2[c * 4 + 2][r] = v.z; As2[c * 4 + 3][r] = v.w;
        }
        // load W_hh tile: 64 n-rows x 32 k (512 float4 tasks)
        #pragma unroll
        for (int it = 0; it < 2; it++) {
            int task = tid + it * 256;
            int r = task >> 3, c = task & 7;
            int grow = (r >> 4) * Hd + jt * 16 + (r & 15);
            float4 v = *reinterpret_cast<const float4*>(
                Whh + (size_t)grow * Hd + kc + c * 4);
            Bs2[c * 4 + 0][r] = v.x; Bs2[c * 4 + 1][r] = v.y;
            Bs2[c * 4 + 2][r] = v.z; Bs2[c * 4 + 3][r] = v.w;
        }
        __syncthreads();

        #pragma unroll
        for (int k = 0; k < 32; k++) {
            float ra0 = As2[k][tr * 2 + 0];
            float ra1 = As2[k][tr * 2 + 1];
            float rb[4];
            #pragma unroll
            for (int j = 0; j < 4; j++) rb[j] = Bs2[k][tc * 4 + j];
            #pragma unroll
            for (int j = 0; j < 4; j++) {
                acc[0][j] = fmaf(ra0, rb[j], acc[0][j]);
                acc[1][j] = fmaf(ra1, rb[j], acc[1][j]);
            }
        }
        __syncthreads();
    }

    // add xg + b_hh, stash gates in smem
    #pragma unroll
    for (int i = 0; i < 2; i++) {
        int m = tr * 2 + i;
        #pragma unroll
        for (int j = 0; j < 4; j++) {
            int n = tc * 4 + j;
            int gcol = (n >> 4) * Hd + jt * 16 + (n & 15);
            Gs[m][n] = acc[i][j] + xg_t[(size_t)(b0 + m) * H4 + gcol] + bhh[gcol];
        }
    }
    __syncthreads();

    // cell update: 32 b x 16 jj
    #pragma unroll
    for (int it = 0; it < 2; it++) {
        int task = tid + it * 256;
        int bl = task >> 4, jj = task & 15;
        float ig = sigmoidf_(Gs[bl][jj]);
        float fg = sigmoidf_(Gs[bl][16 + jj]);
        float gg = tanhf(Gs[bl][32 + jj]);
        float og = sigmoidf_(Gs[bl][48 + jj]);
        size_t idx = (size_t)(b0 + bl) * Hd + jt * 16 + jj;
        float c = fmaf(fg, g_c[idx], ig * gg);
        g_c[idx] = c;
        float h = og * tanhf(c);
        g_h[idx] = h;
        g_hidden[((size_t)(b0 + bl) * Tl + t) * Hd + jt * 16 + jj] = h;
    }
}

// ---------------- launch --------------------------------------------------------
extern "C" void kernel_launch(void* const* d_in, const int* in_sizes, int n_in,
                              void* d_out, int out_size)
{
    const float* features = (const float*)d_in[0];   // [B,F]
    const int*   seqs     = (const int*)  d_in[1];   // [B,T-1]
    const float* W_in  = (const float*)d_in[3];      // [E,F]
    const float* b_in  = (const float*)d_in[4];      // [E]
    const float* emb   = (const float*)d_in[5];      // [V,E]
    const float* W_ih  = (const float*)d_in[6];      // [4H,E]
    const float* W_hh  = (const float*)d_in[7];      // [4H,H]
    const float* b_ih  = (const float*)d_in[8];      // [4H]
    const float* b_hh  = (const float*)d_in[9];      // [4H]
    const float* W_out = (const float*)d_in[10];     // [V,H]
    const float* b_out = (const float*)d_in[11];     // [V]
    float* out = (float*)d_out;                      // [B,T,V]

    float *p_seq, *p_xg, *p_hidden;
    cudaGetSymbolAddress((void**)&p_seq,    g_seq);
    cudaGetSymbolAddress((void**)&p_xg,     g_xg);
    cudaGetSymbolAddress((void**)&p_hidden, g_hidden);
    __nv_bfloat16 *p_feat, *p_Win, *p_sseq, *p_Wih, *p_hid, *p_Wout;
    cudaGetSymbolAddress((void**)&p_feat, s_feat);
    cudaGetSymbolAddress((void**)&p_Win,  s_Win);
    cudaGetSymbolAddress((void**)&p_sseq, s_seq);
    cudaGetSymbolAddress((void**)&p_Wih,  s_Wih);
    cudaGetSymbolAddress((void**)&p_hid,  s_hid);
    cudaGetSymbolAddress((void**)&p_Wout, s_Wout);

    const int TPB = 256;
    auto nb = [](size_t n, int t) { return (int)((n + t - 1) / t); };

    // 1) split features / W_in, x0 GEMM -> g_seq rows [0,128)  (t=0 slice)
    split3<0><<<nb((size_t)Bb * Fdim, TPB), TPB>>>(features, p_feat, Bb, Fdim);
    split3<1><<<nb((size_t)Ed * Fdim, TPB), TPB>>>(W_in, p_Win, Ed, Fdim);
    {
        dim3 grid(Ed / 128, Bb / 128);   // (4,1)
        gemm_bf16<<<grid, 256>>>(p_feat, p_Win, b_in, p_seq, Bb, Ed, K3F);
    }

    // 2) gather embeddings for t = 1..T-1
    gather_emb<<<(Tl - 1) * Bb, 128>>>(seqs, emb);

    // 3) split seq / W_ih, xg GEMM  [5120, 2048]
    split3<0><<<nb((size_t)BT * Ed, TPB), TPB>>>(p_seq, p_sseq, BT, Ed);
    split3<1><<<nb((size_t)H4 * Ed, TPB), TPB>>>(W_ih, p_Wih, H4, Ed);
    {
        dim3 grid(H4 / 128, BT / 128);   // (16,40)
        gemm_bf16<<<grid, 256>>>(p_sseq, p_Wih, b_ih, p_xg, BT, H4, K3E);
    }

    // 4) init h, c = 0
    init_state<<<(Bb * Hd + 255) / 256, 256>>>();

    // 5) recurrence: 40 fused steps
    for (int t = 0; t < Tl; t++) {
        dim3 grid(32, 4);
        lstm_step<<<grid, 256>>>(W_hh, b_hh, p_xg + (size_t)t * Bb * H4, t);
    }

    // 6) split hiddens / W_out, output GEMM  [5120, 10000]
    split3<0><<<nb((size_t)BT * Hd, TPB), TPB>>>(p_hidden, p_hid, BT, Hd);
    split3<1><<<nb((size_t)Vd * Hd, TPB), TPB>>>(W_out, p_Wout, Vd, Hd);
    {
        dim3 grid((Vd + 127) / 128, BT / 128);   // (79,40)
        gemm_bf16<<<grid, 256>>>(p_hid, p_Wout, b_out, out, BT, Vd, K3E);
    }
}